// round 2
// baseline (speedup 1.0000x reference)
#include <cuda_runtime.h>
#include <cstdint>
#include <cstddef>

// ---------------- problem constants ----------------
#define D_MODEL   1024
#define D_PROJ    256
#define MTILE     128                  // rows per CTA
#define NCHUNKS   32                   // K chunks of 32 fp32 (128B per row)
#define EPS1      1e-5f

// smem map (bytes):
//   [0, 4096)      suv: u[256] v[256] g2[256] b2[256]
//   [4096, 6144)   s1p[256] s2p[256]   (LN1 partials)
//   [6144, 7168)   ca[128] cb[128]
//   [8192, ...)    3 pipeline stages (A 16KB + B 32KB each)
//   epilogue reuses stage0: rowacc[128][4][2] (4KB), mu2[128], rs2[128]
#define SMEM_STAGE_OFF 8192
#define A_BYTES  (128 * 32 * 4)        // 16384
#define B_BYTES  (256 * 32 * 4)        // 32768
#define STAGE_BYTES (A_BYTES + B_BYTES)
#define SMEM_BYTES (SMEM_STAGE_OFF + 3 * STAGE_BYTES)   // 155648

// ---------------- device scratch ----------------
// g_Wp layout: [p][kc*32 + s] where storage slot s holds k_local = 16h + c + 4j
// for s = 16h + 4c + j  (so a 16B group feeds two mma k-steps).
__device__ float g_Wp[D_PROJ * D_MODEL];
__device__ float g_u[D_PROJ];
__device__ float g_v[D_PROJ];

// ---------------- helpers ----------------
static __device__ __forceinline__ uint32_t smem_u32(const void* p) {
    uint32_t a;
    asm("{ .reg .u64 t; cvta.to.shared.u64 t, %1; cvt.u32.u64 %0, t; }" : "=r"(a) : "l"(p));
    return a;
}

#define CP_COMMIT() asm volatile("cp.async.commit_group;" ::: "memory")

static __device__ __forceinline__ uint32_t f2tf32(float f) {
    uint32_t u;
    asm("cvt.rna.tf32.f32 %0, %1;" : "=r"(u) : "f"(f));
    return u;
}

#define MMA_TF32(d, a0, a1, a2, a3, b0, b1)                                   \
    asm volatile("mma.sync.aligned.m16n8k8.row.col.f32.tf32.tf32.f32 "        \
        "{%0,%1,%2,%3}, {%4,%5,%6,%7}, {%8,%9}, {%0,%1,%2,%3};"               \
        : "+f"((d)[0]), "+f"((d)[1]), "+f"((d)[2]), "+f"((d)[3])              \
        : "r"(a0), "r"(a1), "r"(a2), "r"(a3), "r"(b0), "r"(b1))

#define LDS128F(v, addr)                                                      \
    asm volatile("ld.shared.v4.f32 {%0,%1,%2,%3}, [%4];"                      \
        : "=f"((v).x), "=f"((v).y), "=f"((v).z), "=f"((v).w) : "r"(addr))

#define LDS128U(r0, r1, r2, r3, addr)                                         \
    asm volatile("ld.shared.v4.b32 {%0,%1,%2,%3}, [%4];"                      \
        : "=r"(r0), "=r"(r1), "=r"(r2), "=r"(r3) : "r"(addr))

// ---------------- prep: W' = g1.*W (tf32-rna), permuted layout; u, v ----------------
__global__ void __launch_bounds__(256) prep_kernel(
    const float* __restrict__ W, const float* __restrict__ g1,
    const float* __restrict__ b1, const float* __restrict__ bias)
{
    __shared__ float ru[8], rv[8];
    int p = blockIdx.x, t = threadIdx.x;
    const float* wrow = W + (size_t)p * D_MODEL;
    float u = 0.f, v = 0.f;
#pragma unroll
    for (int i = 0; i < 4; ++i) {
        int d = t + i * 256;
        float w  = wrow[d];
        float gw = g1[d] * w;
        u += gw;
        v += b1[d] * w;
        // permuted store: natural k_local kk -> slot s = 16h + 4c + j
        int kc = d >> 5, kk = d & 31;
        int h = kk >> 4, c = kk & 3, j = (kk >> 2) & 3;
        int s = (h << 4) | (c << 2) | j;
        g_Wp[(size_t)p * D_MODEL + kc * 32 + s] = __uint_as_float(f2tf32(gw));
    }
#pragma unroll
    for (int o = 16; o > 0; o >>= 1) {
        u += __shfl_xor_sync(0xFFFFFFFFu, u, o);
        v += __shfl_xor_sync(0xFFFFFFFFu, v, o);
    }
    if ((t & 31) == 0) { ru[t >> 5] = u; rv[t >> 5] = v; }
    __syncthreads();
    if (t == 0) {
        float uu = 0.f, vv = 0.f;
#pragma unroll
        for (int i = 0; i < 8; ++i) { uu += ru[i]; vv += rv[i]; }
        g_u[p] = uu;
        g_v[p] = vv + bias[p];
    }
}

// ---------------- chunk loader ----------------
__device__ __forceinline__ void load_chunk(uint32_t sb, const char* xb, const char* wb,
                                           int tid, int kc, int stg)
{
    uint32_t abase = sb + SMEM_STAGE_OFF + (uint32_t)stg * STAGE_BYTES;
    uint32_t bbase = abase + A_BYTES;
    // A: 4096 floats via 4B cp.async with on-the-fly k-permutation + swizzle
    const char* xk = xb + (size_t)kc * 128;
#pragma unroll
    for (int i = 0; i < 16; ++i) {
        int g = i * 256 + tid;
        int r = g >> 5, kk = g & 31;                 // warp covers one 128B row
        int h = kk >> 4, c = kk & 3, j = (kk >> 2) & 3;
        int s = (h << 4) | (c << 2) | j;
        uint32_t Gp = (uint32_t)((s >> 2) ^ (r & 7));
        uint32_t dst = abase + (uint32_t)r * 128 + Gp * 16 + (uint32_t)(s & 3) * 4;
        asm volatile("cp.async.ca.shared.global [%0], [%1], 4;"
                     :: "r"(dst), "l"(xk + (size_t)r * 4096 + (size_t)kk * 4));
    }
    // B: 8192 floats via 16B cp.async (g_Wp already permuted)
    const char* wk = wb + (size_t)kc * 128;
#pragma unroll
    for (int i = 0; i < 8; ++i) {
        int e = i * 256 + tid;
        int p = e >> 3, q = e & 7;
        uint32_t dst = bbase + (uint32_t)p * 128 + (uint32_t)((q ^ (p & 7)) * 16);
        asm volatile("cp.async.cg.shared.global [%0], [%1], 16;"
                     :: "r"(dst), "l"(wk + (size_t)p * 4096 + (size_t)q * 16));
    }
}

// ---------------- main fused kernel ----------------
__global__ void __launch_bounds__(256, 1) fused_kernel(
    const float* __restrict__ x,
    const float* __restrict__ g2v, const float* __restrict__ b2v,
    float* __restrict__ out)
{
    extern __shared__ char smem[];
    const uint32_t sb = smem_u32(smem);
    const int tid  = threadIdx.x;
    const int lane = tid & 31;
    const int wid  = tid >> 5;
    const int wm   = wid >> 2;          // 0..1  (m warp)
    const int wn   = wid & 3;           // 0..3  (n warp)
    const int qt   = lane & 3;          // lane % 4
    const int qr   = lane >> 2;         // lane / 4

    float* suv = (float*)smem;          // u, v, g2, b2
    suv[tid]       = g_u[tid];
    suv[256 + tid] = g_v[tid];
    suv[512 + tid] = g2v[tid];
    suv[768 + tid] = b2v[tid];

    const size_t row0 = (size_t)blockIdx.x * MTILE;
    const char* xb = (const char*)(x + row0 * D_MODEL);
    const char* wb = (const char*)g_Wp;

    float acc[4][8][4];
#pragma unroll
    for (int a = 0; a < 4; ++a)
#pragma unroll
        for (int b = 0; b < 8; ++b)
#pragma unroll
            for (int c = 0; c < 4; ++c) acc[a][b][c] = 0.f;

    float s1 = 0.f, s2 = 0.f;           // LN1 partials: row tid&127, half tid>>7

    load_chunk(sb, xb, wb, tid, 0, 0); CP_COMMIT();
    load_chunk(sb, xb, wb, tid, 1, 1); CP_COMMIT();

#pragma unroll 1
    for (int kc = 0; kc < NCHUNKS; ++kc) {
        const int stg = kc % 3;
        asm volatile("cp.async.wait_group 1;" ::: "memory");
        __syncthreads();                          // all warps done with stage (kc-1)%3
        if (kc + 2 < NCHUNKS) load_chunk(sb, xb, wb, tid, kc + 2, (kc + 2) % 3);
        CP_COMMIT();

        const uint32_t abase = sb + SMEM_STAGE_OFF + (uint32_t)stg * STAGE_BYTES;
        const uint32_t bbase = abase + A_BYTES;

        // LN1 stats from the A tile (order-invariant)
        {
            int r  = tid & 127;
            int hh = tid >> 7;
#pragma unroll
            for (int i = 0; i < 4; ++i) {
                uint32_t G = (uint32_t)(hh * 4 + i);
                uint32_t addr = abase + (uint32_t)r * 128 + ((G ^ (uint32_t)(r & 7)) * 16);
                float4 vv; LDS128F(vv, addr);
                s1 += (vv.x + vv.y) + (vv.z + vv.w);
                s2 += (vv.x * vv.x + vv.y * vv.y) + (vv.z * vv.z + vv.w * vv.w);
            }
        }

        // MMA over the chunk: two 16-wide halves, each = 2 k-steps of m16n8k8
#pragma unroll
        for (int h = 0; h < 2; ++h) {
            const uint32_t G = (uint32_t)(qt + 4 * h);
            uint32_t bfr[8][4];
#pragma unroll
            for (int nt = 0; nt < 8; ++nt) {
                int n = wn * 64 + nt * 8 + qr;
                uint32_t addr = bbase + (uint32_t)n * 128 + ((G ^ (uint32_t)(n & 7)) * 16);
                LDS128U(bfr[nt][0], bfr[nt][1], bfr[nt][2], bfr[nt][3], addr);
            }
#pragma unroll
            for (int mt = 0; mt < 4; ++mt) {
                int r0 = wm * 64 + mt * 16 + qr;
                int r8 = r0 + 8;
                float4 alo, ahi;
                LDS128F(alo, abase + (uint32_t)r0 * 128 + ((G ^ (uint32_t)(r0 & 7)) * 16));
                LDS128F(ahi, abase + (uint32_t)r8 * 128 + ((G ^ (uint32_t)(r8 & 7)) * 16));
                uint32_t a0s0 = f2tf32(alo.x), a2s0 = f2tf32(alo.y);
                uint32_t a0s1 = f2tf32(alo.z), a2s1 = f2tf32(alo.w);
                uint32_t a1s0 = f2tf32(ahi.x), a3s0 = f2tf32(ahi.y);
                uint32_t a1s1 = f2tf32(ahi.z), a3s1 = f2tf32(ahi.w);
#pragma unroll
                for (int nt = 0; nt < 8; ++nt) {
                    MMA_TF32(acc[mt][nt], a0s0, a1s0, a2s0, a3s0, bfr[nt][0], bfr[nt][1]);
                    MMA_TF32(acc[mt][nt], a0s1, a1s1, a2s1, a3s1, bfr[nt][2], bfr[nt][3]);
                }
            }
        }
    }

    // ---------------- LN1 finalize ----------------
    float* s1p = (float*)(smem + 4096);
    float* s2p = s1p + 256;
    s1p[tid] = s1; s2p[tid] = s2;
    __syncthreads();

    float* ca = (float*)(smem + 6144);
    float* cb = ca + 128;
    float* rowacc = (float*)(smem + SMEM_STAGE_OFF);            // [128][4] float2
    float* mu2a = (float*)(smem + SMEM_STAGE_OFF + 4096);
    float* rs2a = mu2a + 128;

    if (tid < 128) {
        float a = s1p[tid] + s1p[tid + 128];
        float b = s2p[tid] + s2p[tid + 128];
        float mu  = a * (1.0f / (float)D_MODEL);
        float var = fmaf(-mu, mu, b * (1.0f / (float)D_MODEL));
        float rs  = rsqrtf(var + EPS1);
        ca[tid] = rs;
        cb[tid] = -mu * rs;
    }
    rowacc[tid] = 0.f; rowacc[tid + 256] = 0.f;
    rowacc[tid + 512] = 0.f; rowacc[tid + 768] = 0.f;
    __syncthreads();

    // ---------------- h = ca*acc + cb*u + v; LN2 partial sums ----------------
#pragma unroll
    for (int mt = 0; mt < 4; ++mt) {
#pragma unroll
        for (int b = 0; b < 2; ++b) {
            int rr = wm * 64 + mt * 16 + qr + 8 * b;
            float cav = ca[rr], cbv = cb[rr];
            float t1 = 0.f, t2 = 0.f;
#pragma unroll
            for (int nt = 0; nt < 8; ++nt) {
                int p0 = wn * 64 + nt * 8 + 2 * qt;
                float h0 = fmaf(cav, acc[mt][nt][2 * b],     fmaf(cbv, suv[p0],     suv[256 + p0]));
                float h1 = fmaf(cav, acc[mt][nt][2 * b + 1], fmaf(cbv, suv[p0 + 1], suv[256 + p0 + 1]));
                acc[mt][nt][2 * b]     = h0;
                acc[mt][nt][2 * b + 1] = h1;
                t1 += h0 + h1;
                t2 += h0 * h0 + h1 * h1;
            }
            t1 += __shfl_xor_sync(0xFFFFFFFFu, t1, 1);
            t2 += __shfl_xor_sync(0xFFFFFFFFu, t2, 1);
            t1 += __shfl_xor_sync(0xFFFFFFFFu, t1, 2);
            t2 += __shfl_xor_sync(0xFFFFFFFFu, t2, 2);
            if (qt == 0) {
                rowacc[(rr * 4 + wn) * 2]     = t1;
                rowacc[(rr * 4 + wn) * 2 + 1] = t2;
            }
        }
    }
    __syncthreads();

    if (tid < 128) {
        float t1 = 0.f, t2 = 0.f;
#pragma unroll
        for (int w = 0; w < 4; ++w) {
            t1 += rowacc[(tid * 4 + w) * 2];
            t2 += rowacc[(tid * 4 + w) * 2 + 1];
        }
        float mu  = t1 * (1.0f / (float)D_PROJ);
        float var = fmaf(-mu, mu, t2 * (1.0f / (float)D_PROJ));
        mu2a[tid] = mu;
        rs2a[tid] = rsqrtf(var + EPS1);
    }
    __syncthreads();

    // ---------------- normalize + store ----------------
    float* outp = out + row0 * D_PROJ;
#pragma unroll
    for (int mt = 0; mt < 4; ++mt) {
#pragma unroll
        for (int b = 0; b < 2; ++b) {
            int rr = wm * 64 + mt * 16 + qr + 8 * b;
            float mu = mu2a[rr], rs = rs2a[rr];
#pragma unroll
            for (int nt = 0; nt < 8; ++nt) {
                int p0 = wn * 64 + nt * 8 + 2 * qt;
                float o0 = fmaf((acc[mt][nt][2 * b]     - mu) * rs, suv[512 + p0],     suv[768 + p0]);
                float o1 = fmaf((acc[mt][nt][2 * b + 1] - mu) * rs, suv[512 + p0 + 1], suv[768 + p0 + 1]);
                float2 o = make_float2(o0, o1);
                *(float2*)(outp + (size_t)rr * D_PROJ + p0) = o;
            }
        }
    }
}

// ---------------- launch ----------------
extern "C" void kernel_launch(void* const* d_in, const int* in_sizes, int n_in,
                              void* d_out, int out_size)
{
    const float* x    = (const float*)d_in[0];
    const float* g1   = (const float*)d_in[1];
    const float* b1   = (const float*)d_in[2];
    const float* W    = (const float*)d_in[3];
    const float* bias = (const float*)d_in[4];
    const float* g2   = (const float*)d_in[5];
    const float* b2   = (const float*)d_in[6];
    float* out = (float*)d_out;

    int n_tok = in_sizes[0] / D_MODEL;          // 65536
    int grid  = n_tok / MTILE;                  // 512

    prep_kernel<<<D_PROJ, 256>>>(W, g1, b1, bias);

    cudaFuncSetAttribute(fused_kernel, cudaFuncAttributeMaxDynamicSharedMemorySize, SMEM_BYTES);
    fused_kernel<<<grid, 256, SMEM_BYTES>>>(x, g2, b2, out);
}